// round 1
// baseline (speedup 1.0000x reference)
#include <cuda_runtime.h>
#include <cstdint>

// Scratch accumulators (no device allocation allowed).
__device__ double g_sum2;
__device__ unsigned long long g_cnt;

__global__ void mml_zero_kernel() {
    g_sum2 = 0.0;
    g_cnt = 0ULL;
}

__global__ void __launch_bounds__(256) mml_reduce_kernel(
    const float4* __restrict__ inp,
    const float4* __restrict__ tgt,
    const int4* __restrict__ msk,
    long long nvec)
{
    float sum = 0.0f;
    unsigned int cnt = 0;

    long long stride = (long long)gridDim.x * blockDim.x;
    for (long long i = (long long)blockIdx.x * blockDim.x + threadIdx.x;
         i < nvec; i += stride) {
        float4 a = inp[i];
        float4 b = tgt[i];
        int4   m = msk[i];

        float dx = a.x - b.x;
        float dy = a.y - b.y;
        float dz = a.z - b.z;
        float dw = a.w - b.w;

        if (m.x == 1) { sum = fmaf(dx, dx, sum); cnt++; }
        if (m.y == 1) { sum = fmaf(dy, dy, sum); cnt++; }
        if (m.z == 1) { sum = fmaf(dz, dz, sum); cnt++; }
        if (m.w == 1) { sum = fmaf(dw, dw, sum); cnt++; }
    }

    // Warp reduction
    #pragma unroll
    for (int off = 16; off > 0; off >>= 1) {
        sum += __shfl_down_sync(0xFFFFFFFFu, sum, off);
        cnt += __shfl_down_sync(0xFFFFFFFFu, cnt, off);
    }

    __shared__ float  s_sum[8];
    __shared__ unsigned int s_cnt[8];
    int lane = threadIdx.x & 31;
    int wid  = threadIdx.x >> 5;
    if (lane == 0) { s_sum[wid] = sum; s_cnt[wid] = cnt; }
    __syncthreads();

    if (wid == 0) {
        sum = (lane < 8) ? s_sum[lane] : 0.0f;
        cnt = (lane < 8) ? s_cnt[lane] : 0u;
        #pragma unroll
        for (int off = 4; off > 0; off >>= 1) {
            sum += __shfl_down_sync(0xFFFFFFFFu, sum, off);
            cnt += __shfl_down_sync(0xFFFFFFFFu, cnt, off);
        }
        if (lane == 0) {
            atomicAdd(&g_sum2, (double)sum);
            atomicAdd(&g_cnt, (unsigned long long)cnt);
        }
    }
}

__global__ void mml_finalize_kernel(float* __restrict__ out) {
    out[0] = (float)(g_sum2 / (double)g_cnt);
}

extern "C" void kernel_launch(void* const* d_in, const int* in_sizes, int n_in,
                              void* d_out, int out_size)
{
    const float4* inp = (const float4*)d_in[0];
    const float4* tgt = (const float4*)d_in[1];
    const int4*   msk = (const int4*)d_in[2];
    float* out = (float*)d_out;

    long long n = (long long)in_sizes[0];
    long long nvec = n / 4;  // 25165824 % 4 == 0

    mml_zero_kernel<<<1, 1>>>();

    int threads = 256;
    int blocks = 1024;
    mml_reduce_kernel<<<blocks, threads>>>(inp, tgt, msk, nvec);

    mml_finalize_kernel<<<1, 1>>>(out);
}